// round 16
// baseline (speedup 1.0000x reference)
#include <cuda_runtime.h>
#include <cuda_fp16.h>

#define BB 4
#define TT 32
#define NN 32
#define FF 16
#define GH 64
#define LSTM_IN 2048
#define LSTM_H 4096
#define G4 16384
#define EE 256

typedef unsigned long long u64t;

// Static scratch (no runtime allocation allowed)
__device__ float d_A[NN * NN];
__device__ float d_seq[BB * TT * LSTM_IN];        // GCN output, 1 MB
__device__ float d_XP[BB * TT * G4];              // x_proj, 8 MB
__device__ float d_H[2][BB * LSTM_H];             // hidden ping-pong
__device__ float d_C[BB * LSTM_H];                // cell state
// W_hh fp16 in mma A-fragment order:
// word idx = (((wid*32 + kc)*8 + m)*32 + lane)*4 + ai   (1024 wids, 134MB)
__device__ unsigned d_Wp[1024 * 32 * 8 * 32 * 4];

// ---- f32x2 packed-FMA helpers (full fp32 precision, 2x FFMA rate) ----------
__device__ __forceinline__ void fma2(u64t& d, u64t a, u64t b) {
    asm("fma.rn.f32x2 %0, %1, %2, %0;" : "+l"(d) : "l"(a), "l"(b));
}
__device__ __forceinline__ u64t pkf2(float x, float y) {
    u64t r; asm("mov.b64 %0, {%1, %2};" : "=l"(r) : "f"(x), "f"(y)); return r;
}
__device__ __forceinline__ float2 upk(u64t v) {
    float2 f; asm("mov.b64 {%0, %1}, %2;" : "=f"(f.x), "=f"(f.y) : "l"(v)); return f;
}
__device__ __forceinline__ unsigned su32(const void* p) {
    unsigned a;
    asm("{.reg .u64 t; cvta.to.shared.u64 t, %1; cvt.u32.u64 %0, t;}"
        : "=r"(a) : "l"(p));
    return a;
}
__device__ __forceinline__ float fsig(float x) {
    return 1.f / (1.f + __expf(-x));
}
__device__ __forceinline__ float ftanh(float x) {
    float e = __expf(-2.f * x);
    return (1.f - e) / (1.f + e);
}

// ---------------------------------------------------------------------------
// W_hh fp32 -> fp16 mma-A-fragment permutation.
// Block = one (wid, kc): 16 logical rows r16 (g=r16>>2, ui=r16&3 ->
// physical row R = wid*4 + ui + g*4096), k window [kc*128, +128).
// a0: row=lane/4,   k=2*(lane%4)+{0,1};  a1: row+8, same k
// a2: row=lane/4,   k+8;                 a3: row+8, k+8      (per m16 step)
// ---------------------------------------------------------------------------
__global__ void __launch_bounds__(128) k_cvt3(const float* __restrict__ src) {
    __shared__ float sT[16][132];
    int wid = blockIdx.x >> 5;
    int kc = blockIdx.x & 31;
    int tid = threadIdx.x;

    // load 16 rows x 128 k (coalesced 512B per row)
    #pragma unroll
    for (int i = 0; i < 4; i++) {
        int idx = tid + i * 128;          // 0..511 float4s
        int r16 = idx >> 5;
        int c4 = idx & 31;
        int R = wid * 4 + (r16 & 3) + (r16 >> 2) * 4096;
        float4 v = *(const float4*)(src + (size_t)R * LSTM_H + kc * 128 + c4 * 4);
        sT[r16][c4 * 4 + 0] = v.x;
        sT[r16][c4 * 4 + 1] = v.y;
        sT[r16][c4 * 4 + 2] = v.z;
        sT[r16][c4 * 4 + 3] = v.w;
    }
    __syncthreads();

    unsigned* dst = d_Wp + (size_t)(wid * 32 + kc) * 1024;
    #pragma unroll
    for (int j = 0; j < 8; j++) {
        int ol = tid + j * 128;           // 0..1023 words, coalesced
        int m = ol >> 7;
        int rem = ol & 127;
        int t = rem >> 2;
        int ai = rem & 3;
        int r16 = (t >> 2) + ((ai & 1) ? 8 : 0);
        int k = m * 16 + ((ai >= 2) ? 8 : 0) + (t & 3) * 2;
        __half2 h = __floats2half2_rn(sT[r16][k], sT[r16][k + 1]);
        dst[ol] = *(unsigned*)&h;
    }
}

// ---------------------------------------------------------------------------
// Dense adjacency (sym-norm + self loops); zero h/c. Runtime int32/64 sniff.
// ---------------------------------------------------------------------------
__global__ void k_setup(const long long* __restrict__ e64,
                        const int* __restrict__ e32) {
    __shared__ float sdeg[NN];
    __shared__ float sdinv[NN];
    __shared__ float sA[NN * NN];
    __shared__ int s_is64;
    int tid = threadIdx.x;

    if (tid == 0) s_is64 = 1;
    if (tid < NN) sdeg[tid] = 1.0f;
    for (int i = tid; i < NN * NN; i += blockDim.x) sA[i] = 0.f;
    __syncthreads();
    {
        long long v = e64[tid];
        if (v < 0 || v >= NN) atomicExch(&s_is64, 0);
    }
    __syncthreads();
    int is64 = s_is64;
    {
        int d = is64 ? (int)e64[EE + tid] : e32[EE + tid];
        if (d >= 0 && d < NN) atomicAdd(&sdeg[d], 1.0f);
    }
    __syncthreads();
    if (tid < NN) sdinv[tid] = rsqrtf(sdeg[tid]);
    __syncthreads();
    {
        int s = is64 ? (int)e64[tid]      : e32[tid];
        int d = is64 ? (int)e64[EE + tid] : e32[EE + tid];
        if (s >= 0 && s < NN && d >= 0 && d < NN)
            atomicAdd(&sA[d * NN + s], sdinv[s] * sdinv[d]);
    }
    __syncthreads();
    if (tid < NN) atomicAdd(&sA[tid * NN + tid], sdinv[tid] * sdinv[tid]);
    __syncthreads();
    for (int i = tid; i < NN * NN; i += blockDim.x) d_A[i] = sA[i];
    float* h = &d_H[0][0];
    for (int i = tid; i < 2 * BB * LSTM_H; i += blockDim.x) h[i] = 0.f;
    for (int i = tid; i < BB * LSTM_H; i += blockDim.x) d_C[i] = 0.f;
}

// ---------------------------------------------------------------------------
// Fused LayerNorm + GCN1 + GCN2 per (b,t) slice.
// ---------------------------------------------------------------------------
__global__ void k_gcn(const float* __restrict__ x,
                      const float* __restrict__ ln_g, const float* __restrict__ ln_b,
                      const float* __restrict__ W1, const float* __restrict__ b1,
                      const float* __restrict__ W2, const float* __restrict__ b2) {
    __shared__ float sA[NN * NN];
    __shared__ float sW1[FF * GH];
    __shared__ float sW2[GH * GH];
    __shared__ float sx[NN][FF];
    __shared__ float sb1[NN][GH];
    __shared__ float sb2[NN][GH];
    int tid = threadIdx.x;
    int bt = blockIdx.x;
    const float* xb = x + bt * NN * FF;

    for (int i = tid; i < NN * NN; i += 256) sA[i] = d_A[i];
    for (int i = tid; i < FF * GH; i += 256) sW1[i] = W1[i];
    for (int i = tid; i < GH * GH; i += 256) sW2[i] = W2[i];
    if (tid < NN) {
        float mu = 0.f;
        #pragma unroll
        for (int f = 0; f < FF; f++) mu += xb[tid * FF + f];
        mu *= (1.0f / FF);
        float var = 0.f;
        #pragma unroll
        for (int f = 0; f < FF; f++) { float d = xb[tid * FF + f] - mu; var += d * d; }
        var *= (1.0f / FF);
        float rs = rsqrtf(var + 1e-5f);
        #pragma unroll
        for (int f = 0; f < FF; f++)
            sx[tid][f] = (xb[tid * FF + f] - mu) * rs * ln_g[f] + ln_b[f];
    }
    __syncthreads();
    for (int i = tid; i < NN * GH; i += 256) {
        int n = i >> 6, g = i & 63;
        float s = 0.f;
        #pragma unroll
        for (int f = 0; f < FF; f++) s += sx[n][f] * sW1[f * GH + g];
        sb1[n][g] = s;
    }
    __syncthreads();
    for (int i = tid; i < NN * GH; i += 256) {
        int n = i >> 6, g = i & 63;
        float s = b1[g];
        #pragma unroll
        for (int m = 0; m < NN; m++) s += sA[n * NN + m] * sb1[m][g];
        sb2[n][g] = s;
    }
    __syncthreads();
    for (int i = tid; i < NN * GH; i += 256) {
        int n = i >> 6, g = i & 63;
        float s = 0.f;
        #pragma unroll
        for (int k = 0; k < GH; k++) s += sb2[n][k] * sW2[k * GH + g];
        sb1[n][g] = s;
    }
    __syncthreads();
    for (int i = tid; i < NN * GH; i += 256) {
        int n = i >> 6, g = i & 63;
        float s = b2[g];
        #pragma unroll
        for (int m = 0; m < NN; m++) s += sA[n * NN + m] * sb1[m][g];
        d_seq[bt * LSTM_IN + i] = s;
    }
}

// ---------------------------------------------------------------------------
// x_proj v6 (R12-proven, ~242us): smem-tiled GEMM + register double-buffer.
// Grid 128, block 512 = 16ty x 32tx. Thread: 8 rows x 4 bt.
// ---------------------------------------------------------------------------
#define XP_PAD 132
#define XSMEM (2 * 64 * XP_PAD * 4)
__global__ void __launch_bounds__(512) k_xproj(const float* __restrict__ Wih,
                                               const float* __restrict__ bih,
                                               const float* __restrict__ bhh) {
    extern __shared__ float xsm[];
    float* sW = xsm;                     // [k][132]
    float* sS = xsm + 64 * XP_PAD;       // [k][132]
    int tid = threadIdx.x;
    int m0 = blockIdx.x * 128;
    int ty = tid >> 5;          // row block: rows ty*8..+7
    int tx = tid & 31;          // bt block: tx*4..+3

    u64t acc[4][4];             // [row-pair][bt]
    #pragma unroll
    for (int p = 0; p < 4; p++)
        #pragma unroll
        for (int b = 0; b < 4; b++) acc[p][b] = 0ull;

    int lr = tid >> 2;                  // load row / bt: 0..127
    int lk = (tid & 3) * 16;            // 16 k per thread

    const float4* Wsrc = (const float4*)(Wih + (size_t)(m0 + lr) * LSTM_IN + lk);
    const float4* Ssrc = (const float4*)(d_seq + (size_t)lr * LSTM_IN + lk);

    float4 wb[4], sb[4];
    #pragma unroll
    for (int i = 0; i < 4; i++) { wb[i] = Wsrc[i]; sb[i] = Ssrc[i]; }

    for (int kc = 0; kc < 32; kc++) {
        __syncthreads();   // WAR: previous tile fully consumed
        #pragma unroll
        for (int i = 0; i < 4; i++) {
            int k = lk + i * 4;
            sW[(k + 0) * XP_PAD + lr] = wb[i].x;
            sW[(k + 1) * XP_PAD + lr] = wb[i].y;
            sW[(k + 2) * XP_PAD + lr] = wb[i].z;
            sW[(k + 3) * XP_PAD + lr] = wb[i].w;
            sS[(k + 0) * XP_PAD + lr] = sb[i].x;
            sS[(k + 1) * XP_PAD + lr] = sb[i].y;
            sS[(k + 2) * XP_PAD + lr] = sb[i].z;
            sS[(k + 3) * XP_PAD + lr] = sb[i].w;
        }
        __syncthreads();   // RAW: tile visible
        if (kc < 31) {     // prefetch next tile; latency hides under compute
            const float4* Wn = Wsrc + (kc + 1) * 16;
            const float4* Sn = Ssrc + (kc + 1) * 16;
            #pragma unroll
            for (int i = 0; i < 4; i++) { wb[i] = Wn[i]; sb[i] = Sn[i]; }
        }
        #pragma unroll 4
        for (int k = 0; k < 64; k++) {
            const ulonglong2* wr = (const ulonglong2*)(sW + k * XP_PAD + ty * 8);
            ulonglong2 wA = wr[0], wB = wr[1];        // pairs p0,p1,p2,p3
            float4 s4 = *(const float4*)(sS + k * XP_PAD + tx * 4);
            u64t b0 = pkf2(s4.x, s4.x), b1 = pkf2(s4.y, s4.y);
            u64t b2 = pkf2(s4.z, s4.z), b3 = pkf2(s4.w, s4.w);
            fma2(acc[0][0], wA.x, b0); fma2(acc[0][1], wA.x, b1);
            fma2(acc[0][2], wA.x, b2); fma2(acc[0][3], wA.x, b3);
            fma2(acc[1][0], wA.y, b0); fma2(acc[1][1], wA.y, b1);
            fma2(acc[1][2], wA.y, b2); fma2(acc[1][3], wA.y, b3);
            fma2(acc[2][0], wB.x, b0); fma2(acc[2][1], wB.x, b1);
            fma2(acc[2][2], wB.x, b2); fma2(acc[2][3], wB.x, b3);
            fma2(acc[3][0], wB.y, b0); fma2(acc[3][1], wB.y, b1);
            fma2(acc[3][2], wB.y, b2); fma2(acc[3][3], wB.y, b3);
        }
    }

    float bias[8];
    #pragma unroll
    for (int r = 0; r < 8; r++) {
        int row = m0 + ty * 8 + r;
        bias[r] = bih[row] + bhh[row];
    }
    #pragma unroll
    for (int b = 0; b < 4; b++) {
        int bt = tx * 4 + b;
        float v[8];
        #pragma unroll
        for (int p = 0; p < 4; p++) {
            float2 f = upk(acc[p][b]);
            v[p * 2 + 0] = f.x + bias[p * 2 + 0];
            v[p * 2 + 1] = f.y + bias[p * 2 + 1];
        }
        float4* dst = (float4*)(d_XP + (size_t)bt * G4 + m0 + ty * 8);
        dst[0] = make_float4(v[0], v[1], v[2], v[3]);
        dst[1] = make_float4(v[4], v[5], v[6], v[7]);
    }
}

// ---------------------------------------------------------------------------
// One LSTM step v7: tensor-core mma.sync.m16n8k16 consuming fp16 W straight
// from the cp.async ring (A pre-permuted to fragment order -> plain LDS.128).
// Warp owns 16 gate rows = 4 units x 4 gates; h staged as fp16 [4][4112]
// (B fragment = 1 LDS.32, lanes 16-31 broadcast; N cols 4-7 ignored).
// Grid 128 x 256 thr (8 warps), single wave; 5-stage ring of 4KB chunks.
// smem: h16 33024 + ring 163840 + sD 2048 = 198912 B.
// ---------------------------------------------------------------------------
#define RSTG 5
#define H16S 4112                       // halfs per batch row (pad 16)
#define H16_BYTES 33024
#define RING_BYTES (8 * RSTG * 4096)
#define STEP_SMEM (H16_BYTES + RING_BYTES + 2048)
__global__ void __launch_bounds__(256, 1) k_step(int t) {
    extern __shared__ char sm[];
    __half* h16 = (__half*)sm;                       // [4][4112]
    char* ring = sm + H16_BYTES;
    float* sDall = (float*)(sm + H16_BYTES + RING_BYTES);  // [8 warps][16][4]
    int tid = threadIdx.x;
    int warp = tid >> 5, lane = tid & 31;
    int wid = blockIdx.x * 8 + warp;                 // 0..1023
    const float* hin = d_H[t & 1];
    float* hout = d_H[(t + 1) & 1];

    // ring prologue (issue before h staging so loads fly under it)
    const char* Wg = (const char*)d_Wp + (size_t)wid * 131072;
    unsigned ringL = su32(ring) + warp * (RSTG * 4096) + lane * 128;

#define ISSUE(s, kc) do {                                                   \
    const char* _src = Wg + (kc) * 4096 + lane * 128;                       \
    unsigned _dst = ringL + (s) * 4096;                                     \
    asm volatile(                                                           \
        "cp.async.cg.shared.global [%0], [%8], 16;\n\t"                     \
        "cp.async.cg.shared.global [%1], [%9], 16;\n\t"                     \
        "cp.async.cg.shared.global [%2], [%10], 16;\n\t"                    \
        "cp.async.cg.shared.global [%3], [%11], 16;\n\t"                    \
        "cp.async.cg.shared.global [%4], [%12], 16;\n\t"                    \
        "cp.async.cg.shared.global [%5], [%13], 16;\n\t"                    \
        "cp.async.cg.shared.global [%6], [%14], 16;\n\t"                    \
        "cp.async.cg.shared.global [%7], [%15], 16;\n\t"                    \
        "cp.async.commit_group;"                                            \
        :: "r"(_dst), "r"(_dst + 16), "r"(_dst + 32), "r"(_dst + 48),       \
           "r"(_dst + 64), "r"(_dst + 80), "r"(_dst + 96), "r"(_dst + 112), \
           "l"(_src), "l"(_src + 16), "l"(_src + 32), "l"(_src + 48),       \
           "l"(_src + 64), "l"(_src + 80), "l"(_src + 96), "l"(_src + 112)  \
        : "memory");                                                        \
} while (0)

    ISSUE(0, 0);
    ISSUE(1, 1);
    ISSUE(2, 2);
    ISSUE(3, 3);

    // stage h as fp16: 8192 float2 -> half2; 256 thr x 32
    {
        const float2* h2 = (const float2*)hin;
        #pragma unroll
        for (int i = 0; i < 32; i++) {
            int idx = tid + i * 256;          // 0..8191
            int b = idx >> 11;                // 2048 float2 per batch
            int k2 = idx & 2047;
            float2 v = h2[idx];
            *(__half2*)(h16 + b * H16S + k2 * 2) = __floats2half2_rn(v.x, v.y);
        }
    }
    __syncthreads();

    float c0 = 0.f, c1 = 0.f, c2 = 0.f, c3 = 0.f;
    const char* ringC = ring + warp * (RSTG * 4096);
    int n4 = (lane >> 2) & 3;               // B col (batch), broadcast hi lanes
    const __half* hb = h16 + n4 * H16S + (lane & 3) * 2;

    int stg = 0;
    #pragma unroll 1
    for (int kc = 0; kc < 32; kc++) {
        if (kc <= 28)      asm volatile("cp.async.wait_group 3;" ::: "memory");
        else if (kc == 29) asm volatile("cp.async.wait_group 2;" ::: "memory");
        else if (kc == 30) asm volatile("cp.async.wait_group 1;" ::: "memory");
        else               asm volatile("cp.async.wait_group 0;" ::: "memory");
        const char* stgp = ringC + stg * 4096;
        #pragma unroll
        for (int m = 0; m < 8; m++) {
            uint4 a = *(const uint4*)(stgp + m * 512 + lane * 16);
            int kb = kc * 128 + m * 16;
            unsigned b0 = *(const unsigned*)(hb + kb);
            unsigned b1 = *(const unsigned*)(hb + kb + 8);
            asm volatile(
                "mma.sync.aligned.m16n8k16.row.col.f32.f16.f16.f32 "
                "{%0,%1,%2,%3}, {%4,%5,%6,%7}, {%8,%9}, {%0,%1,%2,%3};"
                : "+f"(c0), "+f"(c1), "+f"(c2), "+f"(c3)
                : "r"(a.x), "r"(a.y), "r"(a.z), "r"(a.w), "r"(b0), "r"(b1));
        }
        if (kc < 28) ISSUE((kc + 4) % RSTG, kc + 4);
        stg = (stg == RSTG - 1) ? 0 : stg + 1;
    }
#undef ISSUE

    // D scatter to smem: c0 (row=lane/4, col=2*(lane%4)), c1 col+1,
    // c2/c3 rows+8. Only cols 0-3 (batches) are real.
    float* myD = sDall + warp * 64;          // [16][4]
    if ((lane & 3) < 2) {
        int row = lane >> 2;
        int col = (lane & 3) * 2;
        myD[row * 4 + col] = c0;
        myD[row * 4 + col + 1] = c1;
        myD[(row + 8) * 4 + col] = c2;
        myD[(row + 8) * 4 + col + 1] = c3;
    }
    __syncwarp();

    if (lane < 16) {
        int ui = lane & 3, b = lane >> 2;
        int u = wid * 4 + ui;
        size_t xb = ((size_t)b * TT + t) * G4;
        float gi = myD[(0 * 4 + ui) * 4 + b] + d_XP[xb + u];
        float gf = myD[(1 * 4 + ui) * 4 + b] + d_XP[xb + u + 4096];
        float gg = myD[(2 * 4 + ui) * 4 + b] + d_XP[xb + u + 8192];
        float go = myD[(3 * 4 + ui) * 4 + b] + d_XP[xb + u + 12288];
        float si = fsig(gi);
        float sf = fsig(gf);
        float so = fsig(go);
        float c = sf * d_C[b * LSTM_H + u] + si * ftanh(gg);
        d_C[b * LSTM_H + u] = c;
        hout[b * LSTM_H + u] = so * ftanh(c);
    }
}

// ---------------------------------------------------------------------------
// Final FC
// ---------------------------------------------------------------------------
__global__ void k_fc(const float* __restrict__ fcW, const float* __restrict__ fcb,
                     float* __restrict__ out) {
    int i = threadIdx.x;  // 0..127
    int b = i >> 5, n = i & 31;
    const float* h = &d_H[0][0] + b * LSTM_H + n * 128;  // T=32 -> parity 0
    float s = 0.f;
    #pragma unroll
    for (int l = 0; l < 128; l++) s += h[l] * fcW[l];
    out[i] = s + fcb[0];
}

extern "C" void kernel_launch(void* const* d_in, const int* in_sizes, int n_in,
                              void* d_out, int out_size) {
    const float* x       = (const float*)d_in[0];
    const void*  ei      = d_in[1];
    const float* ln_g    = (const float*)d_in[2];
    const float* ln_b    = (const float*)d_in[3];
    const float* W1      = (const float*)d_in[4];
    const float* b1      = (const float*)d_in[5];
    const float* W2      = (const float*)d_in[6];
    const float* b2      = (const float*)d_in[7];
    const float* Wih     = (const float*)d_in[8];
    const float* bih     = (const float*)d_in[9];
    const float* Whh     = (const float*)d_in[10];
    const float* bhh     = (const float*)d_in[11];
    const float* fcW     = (const float*)d_in[12];
    const float* fcb     = (const float*)d_in[13];

    static cudaStream_t s1 = nullptr;
    static cudaEvent_t evO = nullptr, evC = nullptr;
    if (!s1) {
        cudaStreamCreateWithFlags(&s1, cudaStreamNonBlocking);
        cudaEventCreateWithFlags(&evO, cudaEventDisableTiming);
        cudaEventCreateWithFlags(&evC, cudaEventDisableTiming);
        cudaFuncSetAttribute(k_step, cudaFuncAttributeMaxDynamicSharedMemorySize, STEP_SMEM);
        cudaFuncSetAttribute(k_xproj, cudaFuncAttributeMaxDynamicSharedMemorySize, XSMEM);
    }

    // Fork s1 from the capture-origin stream; dependency-free W_hh permute
    // overlaps setup+gcn+xproj and joins before the first LSTM step.
    cudaEventRecord(evO, 0);
    cudaStreamWaitEvent(s1, evO, 0);
    k_cvt3<<<1024 * 32, 128, 0, s1>>>(Whh);
    cudaEventRecord(evC, s1);

    k_setup<<<1, 256>>>((const long long*)ei, (const int*)ei);
    k_gcn<<<BB * TT, 256>>>(x, ln_g, ln_b, W1, b1, W2, b2);
    k_xproj<<<128, 512, XSMEM>>>(Wih, bih, bhh);
    cudaStreamWaitEvent(0, evC, 0);
    for (int t = 0; t < TT; t++) k_step<<<128, 256, STEP_SMEM>>>(t);
    k_fc<<<1, 128>>>(fcW, fcb, (float*)d_out);
}

// round 17
// speedup vs baseline: 1.3035x; 1.3035x over previous
#include <cuda_runtime.h>
#include <cuda_fp16.h>

#define BB 4
#define TT 32
#define NN 32
#define FF 16
#define GH 64
#define LSTM_IN 2048
#define LSTM_H 4096
#define G4 16384
#define EE 256

typedef unsigned long long u64t;

// Static scratch (no runtime allocation allowed)
__device__ float d_A[NN * NN];
__device__ float d_seq[BB * TT * LSTM_IN];        // GCN output, 1 MB
__device__ float d_XP[BB * TT * G4];              // x_proj, 8 MB
__device__ float d_H[2][BB * LSTM_H];             // hidden ping-pong
__device__ float d_C[BB * LSTM_H];                // cell state
// W_hh fp16, warp-major: [wid 2048][kc 32][r 8][lane 32] uint2 (4 halfs)
__device__ uint2 d_Wp[2048 * 32 * 8 * 32];

// ---- f32x2 packed-FMA helpers (full fp32 precision, 2x FFMA rate) ----------
__device__ __forceinline__ void fma2(u64t& d, u64t a, u64t b) {
    asm("fma.rn.f32x2 %0, %1, %2, %0;" : "+l"(d) : "l"(a), "l"(b));
}
__device__ __forceinline__ u64t pkf2(float x, float y) {
    u64t r; asm("mov.b64 %0, {%1, %2};" : "=l"(r) : "f"(x), "f"(y)); return r;
}
__device__ __forceinline__ float2 upk(u64t v) {
    float2 f; asm("mov.b64 {%0, %1}, %2;" : "=f"(f.x), "=f"(f.y) : "l"(v)); return f;
}
// half2 -> packed f32x2
__device__ __forceinline__ u64t h2f2(unsigned h2) {
    u64t r;
    asm("{.reg .f16 lo, hi;\n\t"
        " .reg .f32 flo, fhi;\n\t"
        " mov.b32 {lo, hi}, %1;\n\t"
        " cvt.f32.f16 flo, lo;\n\t"
        " cvt.f32.f16 fhi, hi;\n\t"
        " mov.b64 %0, {flo, fhi};}"
        : "=l"(r) : "r"(h2));
    return r;
}
__device__ __forceinline__ unsigned su32(const void* p) {
    unsigned a;
    asm("{.reg .u64 t; cvta.to.shared.u64 t, %1; cvt.u32.u64 %0, t;}"
        : "=r"(a) : "l"(p));
    return a;
}
__device__ __forceinline__ float fsig(float x) {
    return 1.f / (1.f + __expf(-x));
}
__device__ __forceinline__ float ftanh(float x) {
    float e = __expf(-2.f * x);
    return (1.f - e) / (1.f + e);
}

// ---------------------------------------------------------------------------
// fp32 -> fp16 conversion + warp-major permutation of W_hh.
// ---------------------------------------------------------------------------
__global__ void k_cvt2(const float* __restrict__ src) {
    int i = blockIdx.x * blockDim.x + threadIdx.x;   // 0 .. 16777215
    int lane = i & 31;
    int r = (i >> 5) & 7;
    int kc = (i >> 8) & 31;
    int wid = i >> 13;
    int row = wid + r * 2048;
    float4 v = *(const float4*)(src + (size_t)row * LSTM_H + (kc * 32 + lane) * 4);
    union { __half2 h[2]; uint2 u; } o;
    o.h[0] = __floats2half2_rn(v.x, v.y);
    o.h[1] = __floats2half2_rn(v.z, v.w);
    d_Wp[i] = o.u;
}

// ---------------------------------------------------------------------------
// Dense adjacency (sym-norm + self loops); zero h/c. Runtime int32/64 sniff.
// ---------------------------------------------------------------------------
__global__ void k_setup(const long long* __restrict__ e64,
                        const int* __restrict__ e32) {
    __shared__ float sdeg[NN];
    __shared__ float sdinv[NN];
    __shared__ float sA[NN * NN];
    __shared__ int s_is64;
    int tid = threadIdx.x;

    if (tid == 0) s_is64 = 1;
    if (tid < NN) sdeg[tid] = 1.0f;
    for (int i = tid; i < NN * NN; i += blockDim.x) sA[i] = 0.f;
    __syncthreads();
    {
        long long v = e64[tid];
        if (v < 0 || v >= NN) atomicExch(&s_is64, 0);
    }
    __syncthreads();
    int is64 = s_is64;
    {
        int d = is64 ? (int)e64[EE + tid] : e32[EE + tid];
        if (d >= 0 && d < NN) atomicAdd(&sdeg[d], 1.0f);
    }
    __syncthreads();
    if (tid < NN) sdinv[tid] = rsqrtf(sdeg[tid]);
    __syncthreads();
    {
        int s = is64 ? (int)e64[tid]      : e32[tid];
        int d = is64 ? (int)e64[EE + tid] : e32[EE + tid];
        if (s >= 0 && s < NN && d >= 0 && d < NN)
            atomicAdd(&sA[d * NN + s], sdinv[s] * sdinv[d]);
    }
    __syncthreads();
    if (tid < NN) atomicAdd(&sA[tid * NN + tid], sdinv[tid] * sdinv[tid]);
    __syncthreads();
    for (int i = tid; i < NN * NN; i += blockDim.x) d_A[i] = sA[i];
    float* h = &d_H[0][0];
    for (int i = tid; i < 2 * BB * LSTM_H; i += blockDim.x) h[i] = 0.f;
    for (int i = tid; i < BB * LSTM_H; i += blockDim.x) d_C[i] = 0.f;
}

// ---------------------------------------------------------------------------
// Fused LayerNorm + GCN1 + GCN2 per (b,t) slice.
// ---------------------------------------------------------------------------
__global__ void k_gcn(const float* __restrict__ x,
                      const float* __restrict__ ln_g, const float* __restrict__ ln_b,
                      const float* __restrict__ W1, const float* __restrict__ b1,
                      const float* __restrict__ W2, const float* __restrict__ b2) {
    __shared__ float sA[NN * NN];
    __shared__ float sW1[FF * GH];
    __shared__ float sW2[GH * GH];
    __shared__ float sx[NN][FF];
    __shared__ float sb1[NN][GH];
    __shared__ float sb2[NN][GH];
    int tid = threadIdx.x;
    int bt = blockIdx.x;
    const float* xb = x + bt * NN * FF;

    for (int i = tid; i < NN * NN; i += 256) sA[i] = d_A[i];
    for (int i = tid; i < FF * GH; i += 256) sW1[i] = W1[i];
    for (int i = tid; i < GH * GH; i += 256) sW2[i] = W2[i];
    if (tid < NN) {
        float mu = 0.f;
        #pragma unroll
        for (int f = 0; f < FF; f++) mu += xb[tid * FF + f];
        mu *= (1.0f / FF);
        float var = 0.f;
        #pragma unroll
        for (int f = 0; f < FF; f++) { float d = xb[tid * FF + f] - mu; var += d * d; }
        var *= (1.0f / FF);
        float rs = rsqrtf(var + 1e-5f);
        #pragma unroll
        for (int f = 0; f < FF; f++)
            sx[tid][f] = (xb[tid * FF + f] - mu) * rs * ln_g[f] + ln_b[f];
    }
    __syncthreads();
    for (int i = tid; i < NN * GH; i += 256) {
        int n = i >> 6, g = i & 63;
        float s = 0.f;
        #pragma unroll
        for (int f = 0; f < FF; f++) s += sx[n][f] * sW1[f * GH + g];
        sb1[n][g] = s;
    }
    __syncthreads();
    for (int i = tid; i < NN * GH; i += 256) {
        int n = i >> 6, g = i & 63;
        float s = b1[g];
        #pragma unroll
        for (int m = 0; m < NN; m++) s += sA[n * NN + m] * sb1[m][g];
        sb2[n][g] = s;
    }
    __syncthreads();
    for (int i = tid; i < NN * GH; i += 256) {
        int n = i >> 6, g = i & 63;
        float s = 0.f;
        #pragma unroll
        for (int k = 0; k < GH; k++) s += sb2[n][k] * sW2[k * GH + g];
        sb1[n][g] = s;
    }
    __syncthreads();
    for (int i = tid; i < NN * GH; i += 256) {
        int n = i >> 6, g = i & 63;
        float s = b2[g];
        #pragma unroll
        for (int m = 0; m < NN; m++) s += sA[n * NN + m] * sb1[m][g];
        d_seq[bt * LSTM_IN + i] = s;
    }
}

// ---------------------------------------------------------------------------
// x_proj v6 (R12-proven, ~242us): smem-tiled GEMM + register double-buffer.
// Grid 128, block 512 = 16ty x 32tx. Thread: 8 rows x 4 bt.
// ---------------------------------------------------------------------------
#define XP_PAD 132
#define XSMEM (2 * 64 * XP_PAD * 4)
__global__ void __launch_bounds__(512) k_xproj(const float* __restrict__ Wih,
                                               const float* __restrict__ bih,
                                               const float* __restrict__ bhh) {
    extern __shared__ float xsm[];
    float* sW = xsm;                     // [k][132]
    float* sS = xsm + 64 * XP_PAD;       // [k][132]
    int tid = threadIdx.x;
    int m0 = blockIdx.x * 128;
    int ty = tid >> 5;          // row block: rows ty*8..+7
    int tx = tid & 31;          // bt block: tx*4..+3

    u64t acc[4][4];             // [row-pair][bt]
    #pragma unroll
    for (int p = 0; p < 4; p++)
        #pragma unroll
        for (int b = 0; b < 4; b++) acc[p][b] = 0ull;

    int lr = tid >> 2;                  // load row / bt: 0..127
    int lk = (tid & 3) * 16;            // 16 k per thread

    const float4* Wsrc = (const float4*)(Wih + (size_t)(m0 + lr) * LSTM_IN + lk);
    const float4* Ssrc = (const float4*)(d_seq + (size_t)lr * LSTM_IN + lk);

    float4 wb[4], sb[4];
    #pragma unroll
    for (int i = 0; i < 4; i++) { wb[i] = Wsrc[i]; sb[i] = Ssrc[i]; }

    for (int kc = 0; kc < 32; kc++) {
        __syncthreads();   // WAR: previous tile fully consumed
        #pragma unroll
        for (int i = 0; i < 4; i++) {
            int k = lk + i * 4;
            sW[(k + 0) * XP_PAD + lr] = wb[i].x;
            sW[(k + 1) * XP_PAD + lr] = wb[i].y;
            sW[(k + 2) * XP_PAD + lr] = wb[i].z;
            sW[(k + 3) * XP_PAD + lr] = wb[i].w;
            sS[(k + 0) * XP_PAD + lr] = sb[i].x;
            sS[(k + 1) * XP_PAD + lr] = sb[i].y;
            sS[(k + 2) * XP_PAD + lr] = sb[i].z;
            sS[(k + 3) * XP_PAD + lr] = sb[i].w;
        }
        __syncthreads();   // RAW: tile visible
        if (kc < 31) {     // prefetch next tile; latency hides under compute
            const float4* Wn = Wsrc + (kc + 1) * 16;
            const float4* Sn = Ssrc + (kc + 1) * 16;
            #pragma unroll
            for (int i = 0; i < 4; i++) { wb[i] = Wn[i]; sb[i] = Sn[i]; }
        }
        #pragma unroll 4
        for (int k = 0; k < 64; k++) {
            const ulonglong2* wr = (const ulonglong2*)(sW + k * XP_PAD + ty * 8);
            ulonglong2 wA = wr[0], wB = wr[1];        // pairs p0,p1,p2,p3
            float4 s4 = *(const float4*)(sS + k * XP_PAD + tx * 4);
            u64t b0 = pkf2(s4.x, s4.x), b1 = pkf2(s4.y, s4.y);
            u64t b2 = pkf2(s4.z, s4.z), b3 = pkf2(s4.w, s4.w);
            fma2(acc[0][0], wA.x, b0); fma2(acc[0][1], wA.x, b1);
            fma2(acc[0][2], wA.x, b2); fma2(acc[0][3], wA.x, b3);
            fma2(acc[1][0], wA.y, b0); fma2(acc[1][1], wA.y, b1);
            fma2(acc[1][2], wA.y, b2); fma2(acc[1][3], wA.y, b3);
            fma2(acc[2][0], wB.x, b0); fma2(acc[2][1], wB.x, b1);
            fma2(acc[2][2], wB.x, b2); fma2(acc[2][3], wB.x, b3);
            fma2(acc[3][0], wB.y, b0); fma2(acc[3][1], wB.y, b1);
            fma2(acc[3][2], wB.y, b2); fma2(acc[3][3], wB.y, b3);
        }
    }

    float bias[8];
    #pragma unroll
    for (int r = 0; r < 8; r++) {
        int row = m0 + ty * 8 + r;
        bias[r] = bih[row] + bhh[row];
    }
    #pragma unroll
    for (int b = 0; b < 4; b++) {
        int bt = tx * 4 + b;
        float v[8];
        #pragma unroll
        for (int p = 0; p < 4; p++) {
            float2 f = upk(acc[p][b]);
            v[p * 2 + 0] = f.x + bias[p * 2 + 0];
            v[p * 2 + 1] = f.y + bias[p * 2 + 1];
        }
        float4* dst = (float4*)(d_XP + (size_t)bt * G4 + m0 + ty * 8);
        dst[0] = make_float4(v[0], v[1], v[2], v[3]);
        dst[1] = make_float4(v[4], v[5], v[6], v[7]);
    }
}

// ---------------------------------------------------------------------------
// One LSTM step v6 (R12-proven) + PDL: ring prologue reads only launch-
// invariant d_Wp, so it runs BEFORE griddepcontrol.wait and overlaps the
// predecessor step's drain. cp.async 5-stage ring (4 groups in flight),
// lane-parallel MUFU gate tail. Grid 128 x 512 thr, single wave, 224KB smem.
// ---------------------------------------------------------------------------
#define RSTG 5
#define STEP_SMEM (65536 + 16 * RSTG * 2048)
__global__ void __launch_bounds__(512, 1) k_step(int t) {
    extern __shared__ char smem_raw[];
    float* sh = (float*)smem_raw;        // h[4 batches][4096]
    int tid = threadIdx.x;
    const float* hin = d_H[t & 1];
    float* hout = d_H[(t + 1) & 1];

    int wwarp = tid >> 5, lane = tid & 31;
    int wid = blockIdx.x * 16 + wwarp;

    const char* Wg = (const char*)(d_Wp + (size_t)wid * 8192);
    unsigned ringL = su32(smem_raw) + 65536 + wwarp * (RSTG * 2048) + lane * 64;

#define ISSUE(s, kc) do {                                                   \
    const char* _src = Wg + (kc) * 2048 + lane * 64;                        \
    unsigned _dst = ringL + (s) * 2048;                                     \
    asm volatile(                                                           \
        "cp.async.cg.shared.global [%0], [%4], 16;\n\t"                     \
        "cp.async.cg.shared.global [%1], [%5], 16;\n\t"                     \
        "cp.async.cg.shared.global [%2], [%6], 16;\n\t"                     \
        "cp.async.cg.shared.global [%3], [%7], 16;\n\t"                     \
        "cp.async.commit_group;"                                            \
        :: "r"(_dst), "r"(_dst + 16), "r"(_dst + 32), "r"(_dst + 48),       \
           "l"(_src), "l"(_src + 16), "l"(_src + 32), "l"(_src + 48)        \
        : "memory");                                                        \
} while (0)

    // Pre-wait section: W prefetch only (d_Wp is stable across steps).
    ISSUE(0, 0);
    ISSUE(1, 1);
    ISSUE(2, 2);
    ISSUE(3, 3);

    // Block until predecessor kernel's writes (d_H/d_C/d_XP) are visible.
    asm volatile("griddepcontrol.wait;" ::: "memory");

    {
        const float4* h4 = (const float4*)hin;
        float4* s4 = (float4*)sh;
        #pragma unroll
        for (int i = 0; i < 8; i++)
            s4[tid + i * 512] = h4[tid + i * 512];
    }
    __syncthreads();   // h staging complete

    u64t acc[8][4];
    #pragma unroll
    for (int r = 0; r < 8; r++)
        #pragma unroll
        for (int b = 0; b < 4; b++) acc[r][b] = 0ull;

    const ulonglong2* shu = (const ulonglong2*)sh;
    const char* ringC = smem_raw + 65536 + wwarp * (RSTG * 2048);

    int stg = 0;
    #pragma unroll 1
    for (int kc = 0; kc < 32; kc++) {
        if (kc <= 28)      asm volatile("cp.async.wait_group 3;" ::: "memory");
        else if (kc == 29) asm volatile("cp.async.wait_group 2;" ::: "memory");
        else if (kc == 30) asm volatile("cp.async.wait_group 1;" ::: "memory");
        else               asm volatile("cp.async.wait_group 0;" ::: "memory");
        const uint2* wS = (const uint2*)(ringC + stg * 2048);
        int g = kc * 32 + lane;
        ulonglong2 hA[4];
        #pragma unroll
        for (int b = 0; b < 4; b++)
            hA[b] = shu[b * 1024 + g];
        #pragma unroll
        for (int r = 0; r < 8; r++) {
            uint2 w = wS[r * 32 + lane];
            u64t w0 = h2f2(w.x), w1 = h2f2(w.y);
            #pragma unroll
            for (int b = 0; b < 4; b++) {
                fma2(acc[r][b], w0, hA[b].x);
                fma2(acc[r][b], w1, hA[b].y);
            }
        }
        if (kc < 28) ISSUE((kc + 4) % RSTG, kc + 4);
        stg = (stg == RSTG - 1) ? 0 : stg + 1;
    }
#undef ISSUE

    // Allow the next step's pre-wait section to begin scheduling.
    asm volatile("griddepcontrol.launch_dependents;" ::: "memory");

    float fa[8][4];
    #pragma unroll
    for (int r = 0; r < 8; r++)
        #pragma unroll
        for (int b = 0; b < 4; b++) {
            float2 f = upk(acc[r][b]);
            float v = f.x + f.y;
            #pragma unroll
            for (int o = 16; o; o >>= 1) v += __shfl_xor_sync(0xffffffffu, v, o);
            fa[r][b] = v;   // full sum in ALL lanes
        }

    if (lane < 8) {
        int j = lane & 1;           // unit within warp
        int b = lane >> 1;          // batch
        int u = wid + j * 2048;
        size_t xb = ((size_t)b * TT + t) * G4;
        float gi = fa[j][b]     + d_XP[xb + u];
        float gf = fa[j + 2][b] + d_XP[xb + u + 4096];
        float gg = fa[j + 4][b] + d_XP[xb + u + 8192];
        float go = fa[j + 6][b] + d_XP[xb + u + 12288];
        float si = fsig(gi);
        float sf = fsig(gf);
        float so = fsig(go);
        float c = sf * d_C[b * LSTM_H + u] + si * ftanh(gg);
        d_C[b * LSTM_H + u] = c;
        hout[b * LSTM_H + u] = so * ftanh(c);
    }
}

// ---------------------------------------------------------------------------
// Final FC (PDL-aware: waits for last step's writes)
// ---------------------------------------------------------------------------
__global__ void k_fc(const float* __restrict__ fcW, const float* __restrict__ fcb,
                     float* __restrict__ out) {
    asm volatile("griddepcontrol.wait;" ::: "memory");
    int i = threadIdx.x;  // 0..127
    int b = i >> 5, n = i & 31;
    const float* h = &d_H[0][0] + b * LSTM_H + n * 128;  // T=32 -> parity 0
    float s = 0.f;
    #pragma unroll
    for (int l = 0; l < 128; l++) s += h[l] * fcW[l];
    out[i] = s + fcb[0];
}

extern "C" void kernel_launch(void* const* d_in, const int* in_sizes, int n_in,
                              void* d_out, int out_size) {
    const float* x       = (const float*)d_in[0];
    const void*  ei      = d_in[1];
    const float* ln_g    = (const float*)d_in[2];
    const float* ln_b    = (const float*)d_in[3];
    const float* W1      = (const float*)d_in[4];
    const float* b1      = (const float*)d_in[5];
    const float* W2      = (const float*)d_in[6];
    const float* b2      = (const float*)d_in[7];
    const float* Wih     = (const float*)d_in[8];
    const float* bih     = (const float*)d_in[9];
    const float* Whh     = (const float*)d_in[10];
    const float* bhh     = (const float*)d_in[11];
    const float* fcW     = (const float*)d_in[12];
    const float* fcb     = (const float*)d_in[13];

    static cudaStream_t s1 = nullptr;
    static cudaEvent_t evO = nullptr, evC = nullptr;
    if (!s1) {
        cudaStreamCreateWithFlags(&s1, cudaStreamNonBlocking);
        cudaEventCreateWithFlags(&evO, cudaEventDisableTiming);
        cudaEventCreateWithFlags(&evC, cudaEventDisableTiming);
        cudaFuncSetAttribute(k_step, cudaFuncAttributeMaxDynamicSharedMemorySize, STEP_SMEM);
        cudaFuncSetAttribute(k_xproj, cudaFuncAttributeMaxDynamicSharedMemorySize, XSMEM);
    }

    // Fork s1 from the capture-origin stream; dependency-free W_hh convert
    // overlaps setup+gcn+xproj and joins before the first LSTM step.
    cudaEventRecord(evO, 0);
    cudaStreamWaitEvent(s1, evO, 0);
    k_cvt2<<<65536, 256, 0, s1>>>(Whh);
    cudaEventRecord(evC, s1);

    k_setup<<<1, 256>>>((const long long*)ei, (const int*)ei);
    k_gcn<<<BB * TT, 256>>>(x, ln_g, ln_b, W1, b1, W2, b2);
    k_xproj<<<128, 512, XSMEM>>>(Wih, bih, bhh);
    cudaStreamWaitEvent(0, evC, 0);

    // Step 0: full dependency (joins cvt2/xproj). Steps 1..31 + fc: PDL.
    k_step<<<128, 512, STEP_SMEM>>>(0);

    cudaLaunchAttribute pdl[1];
    pdl[0].id = cudaLaunchAttributeProgrammaticStreamSerialization;
    pdl[0].val.programmaticStreamSerializationAllowed = 1;

    for (int t = 1; t < TT; t++) {
        cudaLaunchConfig_t cfg = {};
        cfg.gridDim = dim3(128, 1, 1);
        cfg.blockDim = dim3(512, 1, 1);
        cfg.dynamicSmemBytes = STEP_SMEM;
        cfg.stream = 0;
        cfg.attrs = pdl;
        cfg.numAttrs = 1;
        cudaLaunchKernelEx(&cfg, k_step, t);
    }
    {
        cudaLaunchConfig_t cfg = {};
        cfg.gridDim = dim3(1, 1, 1);
        cfg.blockDim = dim3(128, 1, 1);
        cfg.dynamicSmemBytes = 0;
        cfg.stream = 0;
        cfg.attrs = pdl;
        cfg.numAttrs = 1;
        cudaLaunchKernelEx(&cfg, k_fc, fcW, fcb, (float*)d_out);
    }
}